// round 7
// baseline (speedup 1.0000x reference)
#include <cuda_runtime.h>
#include <cuda_bf16.h>
#include <cstdint>

#define NMAX 50000
#define EMAX 640000
#define D    128
#define PADK 40   // padded smem row (bf16 elems) -> conflict-free frag loads

// ---- scratch (device globals; no allocation allowed) ----
__device__ int   g_deg[NMAX];        // zeroed by k_assign for next replay
__device__ int   g_rowptr[NMAX];
__device__ int   g_rowend[NMAX];
__device__ int   g_cursor[NMAX];
__device__ int   g_col[EMAX];
__device__ float g_inv[NMAX];
__device__ int   g_total;

__device__ __align__(16) __nv_bfloat16 g_gh[(size_t)NMAX * D];   // agg split hi
__device__ __align__(16) __nv_bfloat16 g_gl[(size_t)NMAX * D];   // agg split lo
__device__ __align__(16) __nv_bfloat16 g_xh[(size_t)NMAX * D];   // x split hi
__device__ __align__(16) __nv_bfloat16 g_xl[(size_t)NMAX * D];
__device__ __align__(16) __nv_bfloat16 g_hh[(size_t)NMAX * D];   // h split hi
__device__ __align__(16) __nv_bfloat16 g_hl[(size_t)NMAX * D];
__device__ __align__(16) __nv_bfloat16 g_wh[4 * D * D];          // w1l,w1r,w2l,w2r hi
__device__ __align__(16) __nv_bfloat16 g_wl[4 * D * D];          // lo

// ============================ splits helper ============================
__device__ __forceinline__ void split2(float a, float b,
                                       __nv_bfloat162& hi, __nv_bfloat162& lo) {
    __nv_bfloat16 ha = __float2bfloat16_rn(a);
    __nv_bfloat16 hb = __float2bfloat16_rn(b);
    float la = a - __bfloat162float(ha);
    float lb = b - __bfloat162float(hb);
    hi = __halves2bfloat162(ha, hb);
    lo = __halves2bfloat162(__float2bfloat16_rn(la), __float2bfloat16_rn(lb));
}

// ============================ CSR build (scan-free) ============================
__global__ void k_deg(const int* __restrict__ dst, int E, int Nn) {
    int e = blockIdx.x * blockDim.x + threadIdx.x;
    if (e == 0) g_total = 0;               // reset ticket for k_assign
    if (e < E) {
        unsigned d = (unsigned)dst[e];
        if (d < (unsigned)Nn) atomicAdd(&g_deg[d], 1);
    }
}

// segment starts via atomic ticket (order irrelevant for gather CSR)
__global__ void k_assign(int Nn) {
    int i = blockIdx.x * blockDim.x + threadIdx.x;
    if (i < Nn) {
        int d = g_deg[i];
        int start = atomicAdd(&g_total, d);
        g_rowptr[i] = start;
        g_cursor[i] = start;
        g_rowend[i] = start + d;
        g_inv[i]    = 1.0f / (float)(d > 0 ? d : 1);
        g_deg[i]    = 0;                   // clean for next replay
    }
}

// fused: CSR fill + x split + W split, dispatched by block range
__global__ void k_fill_split(const int* __restrict__ src,
                             const int* __restrict__ dst, int E, int Nn,
                             const float* __restrict__ x,
                             const float* __restrict__ w0, const float* __restrict__ w1,
                             const float* __restrict__ w2, const float* __restrict__ w3,
                             int FB, int XB) {
    int bid = blockIdx.x;
    int tid = threadIdx.x;
    if (bid < FB) {
        int e = bid * 256 + tid;
        if (e < E) {
            unsigned d = (unsigned)dst[e];
            unsigned s = (unsigned)src[e];
            if (d < (unsigned)Nn && s < (unsigned)Nn) {
                int p = atomicAdd(&g_cursor[d], 1);
                g_col[p] = (int)s;
            }
        }
    } else if (bid < FB + XB) {
        int i = (bid - FB) * 256 + tid;    // one float4 per thread
        int total4 = Nn * (D / 4);
        if (i < total4) {
            float4 v = *(const float4*)(x + (size_t)i * 4);
            __nv_bfloat162 h0, l0, h1, l1;
            split2(v.x, v.y, h0, l0);
            split2(v.z, v.w, h1, l1);
            *(__nv_bfloat162*)(g_xh + (size_t)i * 4)     = h0;
            *(__nv_bfloat162*)(g_xh + (size_t)i * 4 + 2) = h1;
            *(__nv_bfloat162*)(g_xl + (size_t)i * 4)     = l0;
            *(__nv_bfloat162*)(g_xl + (size_t)i * 4 + 2) = l1;
        }
    } else {
        int i = (bid - FB - XB) * 256 + tid;   // 0..16383
        if (i < D * D) {
            const float* srcs[4] = {w0, w1, w2, w3};
#pragma unroll
            for (int m = 0; m < 4; m++) {
                float v = srcs[m][i];
                __nv_bfloat16 h = __float2bfloat16_rn(v);
                g_wh[m * D * D + i] = h;
                g_wl[m * D * D + i] = __float2bfloat16_rn(v - __bfloat162float(h));
            }
        }
    }
}

// ============== mean aggregation: one warp per node, MLP=4, split-bf16 output ========
// IN_H: input is the hh/hl split pair (layer 2); else fp32 X (layer 1).
template <bool IN_H>
__global__ void k_agg(const float* __restrict__ X, int Nn) {
    int node = (blockIdx.x * blockDim.x + threadIdx.x) >> 5;
    int lane = threadIdx.x & 31;
    if (node >= Nn) return;
    int r0 = g_rowptr[node];
    int r1 = g_rowend[node];

    auto loadv = [&](int s) -> float4 {
        if (IN_H) {
            size_t o = (size_t)s * D + lane * 4;
            __nv_bfloat162 h0 = *(const __nv_bfloat162*)(g_hh + o);
            __nv_bfloat162 h1 = *(const __nv_bfloat162*)(g_hh + o + 2);
            __nv_bfloat162 l0 = *(const __nv_bfloat162*)(g_hl + o);
            __nv_bfloat162 l1 = *(const __nv_bfloat162*)(g_hl + o + 2);
            return make_float4(__bfloat162float(h0.x) + __bfloat162float(l0.x),
                               __bfloat162float(h0.y) + __bfloat162float(l0.y),
                               __bfloat162float(h1.x) + __bfloat162float(l1.x),
                               __bfloat162float(h1.y) + __bfloat162float(l1.y));
        } else {
            return *(const float4*)(X + (size_t)s * D + lane * 4);
        }
    };

    float4 acc0 = make_float4(0.f, 0.f, 0.f, 0.f);
    float4 acc1 = make_float4(0.f, 0.f, 0.f, 0.f);
    float4 acc2 = make_float4(0.f, 0.f, 0.f, 0.f);
    float4 acc3 = make_float4(0.f, 0.f, 0.f, 0.f);

    int e = r0;
    for (; e + 3 < r1; e += 4) {
        // hoist all 4 index loads, then 4 independent gathers in flight
        int s0 = g_col[e];
        int s1 = g_col[e + 1];
        int s2 = g_col[e + 2];
        int s3 = g_col[e + 3];
        float4 v0 = loadv(s0);
        float4 v1 = loadv(s1);
        float4 v2 = loadv(s2);
        float4 v3 = loadv(s3);
        acc0.x += v0.x; acc0.y += v0.y; acc0.z += v0.z; acc0.w += v0.w;
        acc1.x += v1.x; acc1.y += v1.y; acc1.z += v1.z; acc1.w += v1.w;
        acc2.x += v2.x; acc2.y += v2.y; acc2.z += v2.z; acc2.w += v2.w;
        acc3.x += v3.x; acc3.y += v3.y; acc3.z += v3.z; acc3.w += v3.w;
    }
    // remainder (0..3 edges)
    for (; e < r1; e++) {
        float4 v0 = loadv(g_col[e]);
        acc0.x += v0.x; acc0.y += v0.y; acc0.z += v0.z; acc0.w += v0.w;
    }

    float inv = g_inv[node];
    float a = (acc0.x + acc1.x + acc2.x + acc3.x) * inv;
    float b = (acc0.y + acc1.y + acc2.y + acc3.y) * inv;
    float c = (acc0.z + acc1.z + acc2.z + acc3.z) * inv;
    float d = (acc0.w + acc1.w + acc2.w + acc3.w) * inv;
    __nv_bfloat162 h0, l0, h1, l1;
    split2(a, b, h0, l0);
    split2(c, d, h1, l1);
    size_t base = (size_t)node * D + lane * 4;
    *(__nv_bfloat162*)(g_gh + base)     = h0;
    *(__nv_bfloat162*)(g_gh + base + 2) = h1;
    *(__nv_bfloat162*)(g_gl + base)     = l0;
    *(__nv_bfloat162*)(g_gl + base + 2) = l1;
}

// ============== tensor-core fused dual GEMM (split-bf16, virtual K=768) ==============
__device__ __forceinline__ void mma16816(float c[4], uint32_t a0, uint32_t a1,
                                         uint32_t a2, uint32_t a3,
                                         uint32_t b0, uint32_t b1) {
    asm volatile(
        "mma.sync.aligned.m16n8k16.row.col.f32.bf16.bf16.f32 "
        "{%0,%1,%2,%3}, {%4,%5,%6,%7}, {%8,%9}, {%0,%1,%2,%3};\n"
        : "+f"(c[0]), "+f"(c[1]), "+f"(c[2]), "+f"(c[3])
        : "r"(a0), "r"(a1), "r"(a2), "r"(a3), "r"(b0), "r"(b1));
}

template <int LAYER>   // 1: relu, writes g_hh/g_hl ; 2: writes outp fp32
__global__ void __launch_bounds__(256, 2)
k_mma(const float* __restrict__ bias, float* __restrict__ outp, int Nn)
{
    __shared__ __nv_bfloat16 As[2][128 * PADK];
    __shared__ __nv_bfloat16 Bs[2][128 * PADK];

    const __nv_bfloat16* A2h = (LAYER == 1) ? g_xh : g_hh;
    const __nv_bfloat16* A2l = (LAYER == 1) ? g_xl : g_hl;
    const int wl = (LAYER == 1) ? 0 : 2;
    const int wr = (LAYER == 1) ? 1 : 3;
    const __nv_bfloat16* Wlh = g_wh + wl * D * D;
    const __nv_bfloat16* Wll = g_wl + wl * D * D;
    const __nv_bfloat16* Wrh = g_wh + wr * D * D;
    const __nv_bfloat16* Wrl = g_wl + wr * D * D;

    // virtual-K slabs (6 x 128): Ah@Wh, Al@Wh, Ah@Wl for each of two segments
    const __nv_bfloat16* Aslab[6] = {g_gh, g_gl, g_gh, A2h, A2l, A2h};
    const __nv_bfloat16* Wslab[6] = {Wlh,  Wlh,  Wll,  Wrh,  Wrh,  Wrl};

    int tid = threadIdx.x;
    int m0  = blockIdx.x * 128;
    int warp = tid >> 5, lane = tid & 31;
    int wm = (warp >> 2) * 64;      // 2 warps in m
    int wn = (warp & 3) * 32;       // 4 warps in n
    int g  = lane >> 2, ctg = lane & 3;

    float acc[4][4][4] = {};

    uint4 pa[2], pb[2];
    auto ldg_step = [&](int s) {
        int slab = s >> 2, koff = (s & 3) * 32;
        const __nv_bfloat16* Ap = Aslab[slab];
        const __nv_bfloat16* Wp = Wslab[slab];
#pragma unroll
        for (int l = 0; l < 2; l++) {
            int u = tid + l * 256;
            int row = u >> 2, kq = u & 3;
            int gm = m0 + row;
            uint4 va = make_uint4(0u, 0u, 0u, 0u);
            if (gm < Nn) va = *(const uint4*)(Ap + (size_t)gm * D + koff + kq * 8);
            pa[l] = va;
            pb[l] = *(const uint4*)(Wp + row * D + koff + kq * 8);
        }
    };
    auto sts_step = [&](int buf) {
#pragma unroll
        for (int l = 0; l < 2; l++) {
            int u = tid + l * 256;
            int row = u >> 2, kq = u & 3;
            *(uint4*)(&As[buf][row * PADK + kq * 8]) = pa[l];
            *(uint4*)(&Bs[buf][row * PADK + kq * 8]) = pb[l];
        }
    };
    auto compute = [&](int buf) {
#pragma unroll
        for (int p = 0; p < 2; p++) {
            uint32_t bfr[4][2];
#pragma unroll
            for (int ni = 0; ni < 4; ni++) {
                int n = wn + ni * 8 + g;
                const __nv_bfloat16* bp = &Bs[buf][n * PADK + p * 16 + ctg * 2];
                bfr[ni][0] = *(const uint32_t*)bp;
                bfr[ni][1] = *(const uint32_t*)(bp + 8);
            }
#pragma unroll
            for (int mi = 0; mi < 4; mi++) {
                int r = wm + mi * 16 + g;
                const __nv_bfloat16* ap = &As[buf][r * PADK + p * 16 + ctg * 2];
                uint32_t a0 = *(const uint32_t*)ap;
                uint32_t a1 = *(const uint32_t*)(ap + 8 * PADK);
                uint32_t a2 = *(const uint32_t*)(ap + 8);
                uint32_t a3 = *(const uint32_t*)(ap + 8 * PADK + 8);
#pragma unroll
                for (int ni = 0; ni < 4; ni++)
                    mma16816(acc[mi][ni], a0, a1, a2, a3, bfr[ni][0], bfr[ni][1]);
            }
        }
    };

    ldg_step(0);
    sts_step(0);
    __syncthreads();
    for (int s = 0; s < 24; s++) {
        if (s < 23) ldg_step(s + 1);
        compute(s & 1);
        if (s < 23) sts_step((s + 1) & 1);
        __syncthreads();
    }

    // epilogue
#pragma unroll
    for (int mi = 0; mi < 4; mi++) {
        int r0 = m0 + wm + mi * 16 + g;
        int r1 = r0 + 8;
#pragma unroll
        for (int ni = 0; ni < 4; ni++) {
            int col = wn + ni * 8 + ctg * 2;
            float2 b2 = *(const float2*)(bias + col);
            float v00 = acc[mi][ni][0] + b2.x, v01 = acc[mi][ni][1] + b2.y;
            float v10 = acc[mi][ni][2] + b2.x, v11 = acc[mi][ni][3] + b2.y;
            if (LAYER == 1) {
                v00 = fmaxf(v00, 0.f); v01 = fmaxf(v01, 0.f);
                v10 = fmaxf(v10, 0.f); v11 = fmaxf(v11, 0.f);
                if (r0 < Nn) {
                    size_t o = (size_t)r0 * D + col;
                    __nv_bfloat162 h2, l2; split2(v00, v01, h2, l2);
                    *(__nv_bfloat162*)(g_hh + o) = h2;
                    *(__nv_bfloat162*)(g_hl + o) = l2;
                }
                if (r1 < Nn) {
                    size_t o = (size_t)r1 * D + col;
                    __nv_bfloat162 h2, l2; split2(v10, v11, h2, l2);
                    *(__nv_bfloat162*)(g_hh + o) = h2;
                    *(__nv_bfloat162*)(g_hl + o) = l2;
                }
            } else {
                if (r0 < Nn) *(float2*)(outp + (size_t)r0 * D + col) = make_float2(v00, v01);
                if (r1 < Nn) *(float2*)(outp + (size_t)r1 * D + col) = make_float2(v10, v11);
            }
        }
    }
}

// ============================ launch ============================
extern "C" void kernel_launch(void* const* d_in, const int* in_sizes, int n_in,
                              void* d_out, int out_size)
{
    const float* x   = (const float*)d_in[0];
    const int*   ei  = (const int*)d_in[1];       // int32 (JAX x64 disabled)
    const float* w1l = (const float*)d_in[2];
    const float* b1  = (const float*)d_in[3];
    const float* w1r = (const float*)d_in[4];
    const float* w2l = (const float*)d_in[5];
    const float* b2  = (const float*)d_in[6];
    const float* w2r = (const float*)d_in[7];
    float*       out = (float*)d_out;

    int Nn = in_sizes[0] / D;
    int E  = in_sizes[1] / 2;
    const int* src = ei;
    const int* dst = ei + E;

    int FB = (E + 255) / 256;                  // fill blocks
    int XB = (Nn * (D / 4) + 255) / 256;       // x-split blocks
    int WB = (D * D + 255) / 256;              // W-split blocks

    // CSR build (scan-free) + operand splits: 3 launches
    k_deg<<<FB, 256>>>(dst, E, Nn);
    k_assign<<<(Nn + 255) / 256, 256>>>(Nn);
    k_fill_split<<<FB + XB + WB, 256>>>(src, dst, E, Nn, x, w1l, w1r, w2l, w2r, FB, XB);

    int aggBlocks  = (Nn * 32 + 255) / 256;
    int gemmBlocks = (Nn + 127) / 128;

    // layer 1: agg(x) -> g_gh/g_gl ; h = relu(agg@w1l^T + b1 + x@w1r^T) -> g_hh/g_hl
    k_agg<false><<<aggBlocks, 256>>>(x, Nn);
    k_mma<1><<<gemmBlocks, 256>>>(b1, nullptr, Nn);

    // layer 2: agg(h) -> g_gh/g_gl ; out = agg@w2l^T + b2 + h@w2r^T
    k_agg<true><<<aggBlocks, 256>>>(nullptr, Nn);
    k_mma<2><<<gemmBlocks, 256>>>(b2, out, Nn);
}

// round 8
// speedup vs baseline: 1.1154x; 1.1154x over previous
#include <cuda_runtime.h>
#include <cuda_bf16.h>
#include <cstdint>

#define NMAX 50000
#define EMAX 640000
#define D    128
#define PK   72   // padded smem row stride (bf16) for BK=64 tiles

// ---- scratch (device globals; no allocation allowed) ----
__device__ int   g_deg[NMAX];        // zeroed by k_assign for next replay
__device__ int   g_rowptr[NMAX];
__device__ int   g_rowend[NMAX];
__device__ int   g_cursor[NMAX];
__device__ int   g_col[EMAX];
__device__ float g_inv[NMAX];
__device__ int   g_total;

__device__ __align__(16) __nv_bfloat16 g_gh[(size_t)NMAX * D];   // agg split hi
__device__ __align__(16) __nv_bfloat16 g_gl[(size_t)NMAX * D];   // agg split lo
__device__ __align__(16) __nv_bfloat16 g_xh[(size_t)NMAX * D];   // x split hi
__device__ __align__(16) __nv_bfloat16 g_xl[(size_t)NMAX * D];
__device__ __align__(16) __nv_bfloat16 g_hh[(size_t)NMAX * D];   // h split hi
__device__ __align__(16) __nv_bfloat16 g_hl[(size_t)NMAX * D];
__device__ __align__(16) __nv_bfloat16 g_wh[4 * D * D];          // w1l,w1r,w2l,w2r hi
__device__ __align__(16) __nv_bfloat16 g_wl[4 * D * D];          // lo

// ============================ splits helper ============================
__device__ __forceinline__ void split2(float a, float b,
                                       __nv_bfloat162& hi, __nv_bfloat162& lo) {
    __nv_bfloat16 ha = __float2bfloat16_rn(a);
    __nv_bfloat16 hb = __float2bfloat16_rn(b);
    float la = a - __bfloat162float(ha);
    float lb = b - __bfloat162float(hb);
    hi = __halves2bfloat162(ha, hb);
    lo = __halves2bfloat162(__float2bfloat16_rn(la), __float2bfloat16_rn(lb));
}

// ============================ CSR build (scan-free) ============================
__global__ void k_deg(const int* __restrict__ dst, int E, int Nn) {
    int e = blockIdx.x * blockDim.x + threadIdx.x;
    if (e == 0) g_total = 0;               // reset ticket for k_assign
    if (e < E) {
        unsigned d = (unsigned)dst[e];
        if (d < (unsigned)Nn) atomicAdd(&g_deg[d], 1);
    }
}

__global__ void k_assign(int Nn) {
    int i = blockIdx.x * blockDim.x + threadIdx.x;
    if (i < Nn) {
        int d = g_deg[i];
        int start = atomicAdd(&g_total, d);
        g_rowptr[i] = start;
        g_cursor[i] = start;
        g_rowend[i] = start + d;
        g_inv[i]    = 1.0f / (float)(d > 0 ? d : 1);
        g_deg[i]    = 0;                   // clean for next replay
    }
}

// fused: CSR fill + x split + W split, dispatched by block range
__global__ void k_fill_split(const int* __restrict__ src,
                             const int* __restrict__ dst, int E, int Nn,
                             const float* __restrict__ x,
                             const float* __restrict__ w0, const float* __restrict__ w1,
                             const float* __restrict__ w2, const float* __restrict__ w3,
                             int FB, int XB) {
    int bid = blockIdx.x;
    int tid = threadIdx.x;
    if (bid < FB) {
        int e = bid * 256 + tid;
        if (e < E) {
            unsigned d = (unsigned)dst[e];
            unsigned s = (unsigned)src[e];
            if (d < (unsigned)Nn && s < (unsigned)Nn) {
                int p = atomicAdd(&g_cursor[d], 1);
                g_col[p] = (int)s;
            }
        }
    } else if (bid < FB + XB) {
        int i = (bid - FB) * 256 + tid;    // one float4 per thread
        int total4 = Nn * (D / 4);
        if (i < total4) {
            float4 v = *(const float4*)(x + (size_t)i * 4);
            __nv_bfloat162 h0, l0, h1, l1;
            split2(v.x, v.y, h0, l0);
            split2(v.z, v.w, h1, l1);
            *(__nv_bfloat162*)(g_xh + (size_t)i * 4)     = h0;
            *(__nv_bfloat162*)(g_xh + (size_t)i * 4 + 2) = h1;
            *(__nv_bfloat162*)(g_xl + (size_t)i * 4)     = l0;
            *(__nv_bfloat162*)(g_xl + (size_t)i * 4 + 2) = l1;
        }
    } else {
        int i = (bid - FB - XB) * 256 + tid;   // 0..16383
        if (i < D * D) {
            const float* srcs[4] = {w0, w1, w2, w3};
#pragma unroll
            for (int m = 0; m < 4; m++) {
                float v = srcs[m][i];
                __nv_bfloat16 h = __float2bfloat16_rn(v);
                g_wh[m * D * D + i] = h;
                g_wl[m * D * D + i] = __float2bfloat16_rn(v - __bfloat162float(h));
            }
        }
    }
}

// ============== mean aggregation: one warp per node (R6 form: L2-cap bound) ==========
template <bool IN_H>
__global__ void k_agg(const float* __restrict__ X, int Nn) {
    int node = (blockIdx.x * blockDim.x + threadIdx.x) >> 5;
    int lane = threadIdx.x & 31;
    if (node >= Nn) return;
    int r0 = g_rowptr[node];
    int r1 = g_rowend[node];
    float4 acc0 = make_float4(0.f, 0.f, 0.f, 0.f);
    float4 acc1 = make_float4(0.f, 0.f, 0.f, 0.f);

    auto loadv = [&](int s) -> float4 {
        if (IN_H) {
            size_t o = (size_t)s * D + lane * 4;
            __nv_bfloat162 h0 = *(const __nv_bfloat162*)(g_hh + o);
            __nv_bfloat162 h1 = *(const __nv_bfloat162*)(g_hh + o + 2);
            __nv_bfloat162 l0 = *(const __nv_bfloat162*)(g_hl + o);
            __nv_bfloat162 l1 = *(const __nv_bfloat162*)(g_hl + o + 2);
            return make_float4(__bfloat162float(h0.x) + __bfloat162float(l0.x),
                               __bfloat162float(h0.y) + __bfloat162float(l0.y),
                               __bfloat162float(h1.x) + __bfloat162float(l1.x),
                               __bfloat162float(h1.y) + __bfloat162float(l1.y));
        } else {
            return *(const float4*)(X + (size_t)s * D + lane * 4);
        }
    };

    int e = r0;
    for (; e + 1 < r1; e += 2) {
        int s0 = g_col[e];
        int s1 = g_col[e + 1];
        float4 v0 = loadv(s0);
        float4 v1 = loadv(s1);
        acc0.x += v0.x; acc0.y += v0.y; acc0.z += v0.z; acc0.w += v0.w;
        acc1.x += v1.x; acc1.y += v1.y; acc1.z += v1.z; acc1.w += v1.w;
    }
    if (e < r1) {
        float4 v0 = loadv(g_col[e]);
        acc0.x += v0.x; acc0.y += v0.y; acc0.z += v0.z; acc0.w += v0.w;
    }
    float inv = g_inv[node];
    float a = (acc0.x + acc1.x) * inv;
    float b = (acc0.y + acc1.y) * inv;
    float c = (acc0.z + acc1.z) * inv;
    float d = (acc0.w + acc1.w) * inv;
    __nv_bfloat162 h0, l0, h1, l1;
    split2(a, b, h0, l0);
    split2(c, d, h1, l1);
    size_t base = (size_t)node * D + lane * 4;
    *(__nv_bfloat162*)(g_gh + base)     = h0;
    *(__nv_bfloat162*)(g_gh + base + 2) = h1;
    *(__nv_bfloat162*)(g_gl + base)     = l0;
    *(__nv_bfloat162*)(g_gl + base + 2) = l1;
}

// ============== tensor-core fused dual GEMM (split-bf16, virtual K=768, BK=64) =======
__device__ __forceinline__ void mma16816(float c[4], uint32_t a0, uint32_t a1,
                                         uint32_t a2, uint32_t a3,
                                         uint32_t b0, uint32_t b1) {
    asm volatile(
        "mma.sync.aligned.m16n8k16.row.col.f32.bf16.bf16.f32 "
        "{%0,%1,%2,%3}, {%4,%5,%6,%7}, {%8,%9}, {%0,%1,%2,%3};\n"
        : "+f"(c[0]), "+f"(c[1]), "+f"(c[2]), "+f"(c[3])
        : "r"(a0), "r"(a1), "r"(a2), "r"(a3), "r"(b0), "r"(b1));
}

template <int LAYER>   // 1: relu, writes g_hh/g_hl ; 2: writes outp fp32
__global__ void __launch_bounds__(256, 2)
k_mma(const float* __restrict__ bias, float* __restrict__ outp, int Nn)
{
    // BK=64 double-buffered tiles: 128 rows x 64 k, stride PK=72 bf16
    __shared__ __nv_bfloat16 As[2][128 * PK];
    __shared__ __nv_bfloat16 Bs[2][128 * PK];

    const __nv_bfloat16* A2h = (LAYER == 1) ? g_xh : g_hh;
    const __nv_bfloat16* A2l = (LAYER == 1) ? g_xl : g_hl;
    const int wl = (LAYER == 1) ? 0 : 2;
    const int wr = (LAYER == 1) ? 1 : 3;
    const __nv_bfloat16* Wlh = g_wh + wl * D * D;
    const __nv_bfloat16* Wll = g_wl + wl * D * D;
    const __nv_bfloat16* Wrh = g_wh + wr * D * D;
    const __nv_bfloat16* Wrl = g_wl + wr * D * D;

    // 6 virtual-K slabs of 128: Ah@Wh, Al@Wh, Ah@Wl per segment
    const __nv_bfloat16* Aslab[6] = {g_gh, g_gl, g_gh, A2h, A2l, A2h};
    const __nv_bfloat16* Wslab[6] = {Wlh,  Wlh,  Wll,  Wrh,  Wrh,  Wrl};

    int tid = threadIdx.x;
    int m0  = blockIdx.x * 128;
    int warp = tid >> 5, lane = tid & 31;
    int wm = (warp >> 2) * 64;      // 2 warps in m
    int wn = (warp & 3) * 32;       // 4 warps in n
    int g  = lane >> 2, ctg = lane & 3;

    float acc[4][4][4] = {};

    // per-stage: each thread loads 4 uint4 of A and 4 of B (16KB each tile)
    uint4 pa[4], pb[4];
    auto ldg_step = [&](int s) {
        int slab = s >> 1, koff = (s & 1) * 64;
        const __nv_bfloat16* Ap = Aslab[slab];
        const __nv_bfloat16* Wp = Wslab[slab];
#pragma unroll
        for (int l = 0; l < 4; l++) {
            int u = tid + l * 256;          // 0..1023 uint4 slots
            int row = u >> 3, kq = u & 7;   // 128 rows x 8 chunks
            int gm = m0 + row;
            uint4 va = make_uint4(0u, 0u, 0u, 0u);
            if (gm < Nn) va = *(const uint4*)(Ap + (size_t)gm * D + koff + kq * 8);
            pa[l] = va;
            pb[l] = *(const uint4*)(Wp + row * D + koff + kq * 8);
        }
    };
    auto sts_step = [&](int buf) {
#pragma unroll
        for (int l = 0; l < 4; l++) {
            int u = tid + l * 256;
            int row = u >> 3, kq = u & 7;
            *(uint4*)(&As[buf][row * PK + kq * 8]) = pa[l];
            *(uint4*)(&Bs[buf][row * PK + kq * 8]) = pb[l];
        }
    };
    auto compute = [&](int buf) {
#pragma unroll
        for (int p = 0; p < 4; p++) {       // four k16 phases per BK=64
            uint32_t bfr[4][2];
#pragma unroll
            for (int ni = 0; ni < 4; ni++) {
                int n = wn + ni * 8 + g;
                const __nv_bfloat16* bp = &Bs[buf][n * PK + p * 16 + ctg * 2];
                bfr[ni][0] = *(const uint32_t*)bp;
                bfr[ni][1] = *(const uint32_t*)(bp + 8);
            }
#pragma unroll
            for (int mi = 0; mi < 4; mi++) {
                int r = wm + mi * 16 + g;
                const __nv_bfloat16* ap = &As[buf][r * PK + p * 16 + ctg * 2];
                uint32_t a0 = *(const uint32_t*)ap;
                uint32_t a1 = *(const uint32_t*)(ap + 8 * PK);
                uint32_t a2 = *(const uint32_t*)(ap + 8);
                uint32_t a3 = *(const uint32_t*)(ap + 8 * PK + 8);
#pragma unroll
                for (int ni = 0; ni < 4; ni++)
                    mma16816(acc[mi][ni], a0, a1, a2, a3, bfr[ni][0], bfr[ni][1]);
            }
        }
    };

    ldg_step(0);
    sts_step(0);
    __syncthreads();
    for (int s = 0; s < 12; s++) {          // 6 slabs x 2 halves
        if (s < 11) ldg_step(s + 1);
        compute(s & 1);
        if (s < 11) sts_step((s + 1) & 1);
        __syncthreads();
    }

    // epilogue
#pragma unroll
    for (int mi = 0; mi < 4; mi++) {
        int r0 = m0 + wm + mi * 16 + g;
        int r1 = r0 + 8;
#pragma unroll
        for (int ni = 0; ni < 4; ni++) {
            int col = wn + ni * 8 + ctg * 2;
            float2 b2 = *(const float2*)(bias + col);
            float v00 = acc[mi][ni][0] + b2.x, v01 = acc[mi][ni][1] + b2.y;
            float v10 = acc[mi][ni][2] + b2.x, v11 = acc[mi][ni][3] + b2.y;
            if (LAYER == 1) {
                v00 = fmaxf(v00, 0.f); v01 = fmaxf(v01, 0.f);
                v10 = fmaxf(v10, 0.f); v11 = fmaxf(v11, 0.f);
                if (r0 < Nn) {
                    size_t o = (size_t)r0 * D + col;
                    __nv_bfloat162 h2, l2; split2(v00, v01, h2, l2);
                    *(__nv_bfloat162*)(g_hh + o) = h2;
                    *(__nv_bfloat162*)(g_hl + o) = l2;
                }
                if (r1 < Nn) {
                    size_t o = (size_t)r1 * D + col;
                    __nv_bfloat162 h2, l2; split2(v10, v11, h2, l2);
                    *(__nv_bfloat162*)(g_hh + o) = h2;
                    *(__nv_bfloat162*)(g_hl + o) = l2;
                }
            } else {
                if (r0 < Nn) *(float2*)(outp + (size_t)r0 * D + col) = make_float2(v00, v01);
                if (r1 < Nn) *(float2*)(outp + (size_t)r1 * D + col) = make_float2(v10, v11);
            }
        }
    }
}

// ============================ launch ============================
extern "C" void kernel_launch(void* const* d_in, const int* in_sizes, int n_in,
                              void* d_out, int out_size)
{
    const float* x   = (const float*)d_in[0];
    const int*   ei  = (const int*)d_in[1];       // int32 (JAX x64 disabled)
    const float* w1l = (const float*)d_in[2];
    const float* b1  = (const float*)d_in[3];
    const float* w1r = (const float*)d_in[4];
    const float* w2l = (const float*)d_in[5];
    const float* b2  = (const float*)d_in[6];
    const float* w2r = (const float*)d_in[7];
    float*       out = (float*)d_out;

    int Nn = in_sizes[0] / D;
    int E  = in_sizes[1] / 2;
    const int* src = ei;
    const int* dst = ei + E;

    int FB = (E + 255) / 256;
    int XB = (Nn * (D / 4) + 255) / 256;
    int WB = (D * D + 255) / 256;

    k_deg<<<FB, 256>>>(dst, E, Nn);
    k_assign<<<(Nn + 255) / 256, 256>>>(Nn);
    k_fill_split<<<FB + XB + WB, 256>>>(src, dst, E, Nn, x, w1l, w1r, w2l, w2r, FB, XB);

    int aggBlocks  = (Nn * 32 + 255) / 256;
    int gemmBlocks = (Nn + 127) / 128;

    k_agg<false><<<aggBlocks, 256>>>(x, Nn);
    k_mma<1><<<gemmBlocks, 256>>>(b1, nullptr, Nn);

    k_agg<true><<<aggBlocks, 256>>>(nullptr, Nn);
    k_mma<2><<<gemmBlocks, 256>>>(b2, out, Nn);
}

// round 9
// speedup vs baseline: 1.1301x; 1.0132x over previous
#include <cuda_runtime.h>
#include <cuda_bf16.h>
#include <cstdint>

#define NMAX 50000
#define EMAX 640000
#define D    128
#define PK   72   // padded smem row stride (bf16) for BK=64 tiles

// ---- scratch (device globals; no allocation allowed) ----
__device__ int   g_deg[NMAX];        // zeroed by k_assign for next replay
__device__ int   g_rowptr[NMAX];
__device__ int   g_rowend[NMAX];
__device__ int   g_cursor[NMAX];
__device__ int   g_col[EMAX];
__device__ float g_inv[NMAX];
__device__ int   g_total;

__device__ __align__(16) __nv_bfloat16 g_gh[(size_t)NMAX * D];   // agg split hi
__device__ __align__(16) __nv_bfloat16 g_gl[(size_t)NMAX * D];   // agg split lo
__device__ __align__(16) __nv_bfloat16 g_xh[(size_t)NMAX * D];   // x split hi
__device__ __align__(16) __nv_bfloat16 g_xl[(size_t)NMAX * D];
__device__ __align__(16) __nv_bfloat16 g_hh[(size_t)NMAX * D];   // h split hi
__device__ __align__(16) __nv_bfloat16 g_hl[(size_t)NMAX * D];
__device__ __align__(16) __nv_bfloat16 g_wh[4 * D * D];          // w1l,w1r,w2l,w2r hi
__device__ __align__(16) __nv_bfloat16 g_wl[4 * D * D];          // lo

// ============================ splits helper ============================
__device__ __forceinline__ void split2(float a, float b,
                                       __nv_bfloat162& hi, __nv_bfloat162& lo) {
    __nv_bfloat16 ha = __float2bfloat16_rn(a);
    __nv_bfloat16 hb = __float2bfloat16_rn(b);
    float la = a - __bfloat162float(ha);
    float lb = b - __bfloat162float(hb);
    hi = __halves2bfloat162(ha, hb);
    lo = __halves2bfloat162(__float2bfloat16_rn(la), __float2bfloat16_rn(lb));
}

// ============================ CSR build (scan-free) ============================
__global__ void k_deg(const int* __restrict__ dst, int E, int Nn) {
    int e = blockIdx.x * blockDim.x + threadIdx.x;
    if (e == 0) g_total = 0;               // reset ticket for k_assign
    if (e < E) {
        unsigned d = (unsigned)dst[e];
        if (d < (unsigned)Nn) atomicAdd(&g_deg[d], 1);
    }
}

__global__ void k_assign(int Nn) {
    int i = blockIdx.x * blockDim.x + threadIdx.x;
    if (i < Nn) {
        int d = g_deg[i];
        int start = atomicAdd(&g_total, d);
        g_rowptr[i] = start;
        g_cursor[i] = start;
        g_rowend[i] = start + d;
        g_inv[i]    = 1.0f / (float)(d > 0 ? d : 1);
        g_deg[i]    = 0;                   // clean for next replay
    }
}

// fused: CSR fill + x split + W split, dispatched by block range
__global__ void k_fill_split(const int* __restrict__ src,
                             const int* __restrict__ dst, int E, int Nn,
                             const float* __restrict__ x,
                             const float* __restrict__ w0, const float* __restrict__ w1,
                             const float* __restrict__ w2, const float* __restrict__ w3,
                             int FB, int XB) {
    int bid = blockIdx.x;
    int tid = threadIdx.x;
    if (bid < FB) {
        int e = bid * 256 + tid;
        if (e < E) {
            unsigned d = (unsigned)dst[e];
            unsigned s = (unsigned)src[e];
            if (d < (unsigned)Nn && s < (unsigned)Nn) {
                int p = atomicAdd(&g_cursor[d], 1);
                g_col[p] = (int)s;
            }
        }
    } else if (bid < FB + XB) {
        int i = (bid - FB) * 256 + tid;    // one float4 per thread
        int total4 = Nn * (D / 4);
        if (i < total4) {
            float4 v = *(const float4*)(x + (size_t)i * 4);
            __nv_bfloat162 h0, l0, h1, l1;
            split2(v.x, v.y, h0, l0);
            split2(v.z, v.w, h1, l1);
            *(__nv_bfloat162*)(g_xh + (size_t)i * 4)     = h0;
            *(__nv_bfloat162*)(g_xh + (size_t)i * 4 + 2) = h1;
            *(__nv_bfloat162*)(g_xl + (size_t)i * 4)     = l0;
            *(__nv_bfloat162*)(g_xl + (size_t)i * 4 + 2) = l1;
        }
    } else {
        int i = (bid - FB - XB) * 256 + tid;   // 0..16383
        if (i < D * D) {
            const float* srcs[4] = {w0, w1, w2, w3};
#pragma unroll
            for (int m = 0; m < 4; m++) {
                float v = srcs[m][i];
                __nv_bfloat16 h = __float2bfloat16_rn(v);
                g_wh[m * D * D + i] = h;
                g_wl[m * D * D + i] = __float2bfloat16_rn(v - __bfloat162float(h));
            }
        }
    }
}

// ============== mean aggregation: one warp per node (L2-cap bound — frozen) ==========
template <bool IN_H>
__global__ void k_agg(const float* __restrict__ X, int Nn) {
    int node = (blockIdx.x * blockDim.x + threadIdx.x) >> 5;
    int lane = threadIdx.x & 31;
    if (node >= Nn) return;
    int r0 = g_rowptr[node];
    int r1 = g_rowend[node];
    float4 acc0 = make_float4(0.f, 0.f, 0.f, 0.f);
    float4 acc1 = make_float4(0.f, 0.f, 0.f, 0.f);

    auto loadv = [&](int s) -> float4 {
        if (IN_H) {
            size_t o = (size_t)s * D + lane * 4;
            __nv_bfloat162 h0 = *(const __nv_bfloat162*)(g_hh + o);
            __nv_bfloat162 h1 = *(const __nv_bfloat162*)(g_hh + o + 2);
            __nv_bfloat162 l0 = *(const __nv_bfloat162*)(g_hl + o);
            __nv_bfloat162 l1 = *(const __nv_bfloat162*)(g_hl + o + 2);
            return make_float4(__bfloat162float(h0.x) + __bfloat162float(l0.x),
                               __bfloat162float(h0.y) + __bfloat162float(l0.y),
                               __bfloat162float(h1.x) + __bfloat162float(l1.x),
                               __bfloat162float(h1.y) + __bfloat162float(l1.y));
        } else {
            return *(const float4*)(X + (size_t)s * D + lane * 4);
        }
    };

    int e = r0;
    for (; e + 1 < r1; e += 2) {
        int s0 = g_col[e];
        int s1 = g_col[e + 1];
        float4 v0 = loadv(s0);
        float4 v1 = loadv(s1);
        acc0.x += v0.x; acc0.y += v0.y; acc0.z += v0.z; acc0.w += v0.w;
        acc1.x += v1.x; acc1.y += v1.y; acc1.z += v1.z; acc1.w += v1.w;
    }
    if (e < r1) {
        float4 v0 = loadv(g_col[e]);
        acc0.x += v0.x; acc0.y += v0.y; acc0.z += v0.z; acc0.w += v0.w;
    }
    float inv = g_inv[node];
    float a = (acc0.x + acc1.x) * inv;
    float b = (acc0.y + acc1.y) * inv;
    float c = (acc0.z + acc1.z) * inv;
    float d = (acc0.w + acc1.w) * inv;
    __nv_bfloat162 h0, l0, h1, l1;
    split2(a, b, h0, l0);
    split2(c, d, h1, l1);
    size_t base = (size_t)node * D + lane * 4;
    *(__nv_bfloat162*)(g_gh + base)     = h0;
    *(__nv_bfloat162*)(g_gh + base + 2) = h1;
    *(__nv_bfloat162*)(g_gl + base)     = l0;
    *(__nv_bfloat162*)(g_gl + base + 2) = l1;
}

// ============== tensor-core fused dual GEMM (split-bf16, BK=64, cp.async) ============
__device__ __forceinline__ void mma16816(float c[4], uint32_t a0, uint32_t a1,
                                         uint32_t a2, uint32_t a3,
                                         uint32_t b0, uint32_t b1) {
    asm volatile(
        "mma.sync.aligned.m16n8k16.row.col.f32.bf16.bf16.f32 "
        "{%0,%1,%2,%3}, {%4,%5,%6,%7}, {%8,%9}, {%0,%1,%2,%3};\n"
        : "+f"(c[0]), "+f"(c[1]), "+f"(c[2]), "+f"(c[3])
        : "r"(a0), "r"(a1), "r"(a2), "r"(a3), "r"(b0), "r"(b1));
}

__device__ __forceinline__ void cp16(uint32_t saddr, const void* gaddr, int srcBytes) {
    asm volatile("cp.async.cg.shared.global [%0], [%1], 16, %2;\n"
                 :: "r"(saddr), "l"(gaddr), "r"(srcBytes));
}

template <int LAYER>   // 1: relu, writes g_hh/g_hl ; 2: writes outp fp32
__global__ void __launch_bounds__(256, 2)
k_mma(const float* __restrict__ bias, float* __restrict__ outp, int Nn)
{
    // BK=64 double-buffered tiles: 128 rows x 64 k, stride PK=72 bf16
    __shared__ __nv_bfloat16 As[2][128 * PK];
    __shared__ __nv_bfloat16 Bs[2][128 * PK];

    const __nv_bfloat16* A2h = (LAYER == 1) ? g_xh : g_hh;
    const __nv_bfloat16* A2l = (LAYER == 1) ? g_xl : g_hl;
    const int wl = (LAYER == 1) ? 0 : 2;
    const int wr = (LAYER == 1) ? 1 : 3;
    const __nv_bfloat16* Wlh = g_wh + wl * D * D;
    const __nv_bfloat16* Wll = g_wl + wl * D * D;
    const __nv_bfloat16* Wrh = g_wh + wr * D * D;
    const __nv_bfloat16* Wrl = g_wl + wr * D * D;

    // 6 virtual-K slabs of 128: Ah@Wh, Al@Wh, Ah@Wl per segment
    const __nv_bfloat16* Aslab[6] = {g_gh, g_gl, g_gh, A2h, A2l, A2h};
    const __nv_bfloat16* Wslab[6] = {Wlh,  Wlh,  Wll,  Wrh,  Wrh,  Wrl};

    int tid = threadIdx.x;
    int m0  = blockIdx.x * 128;
    int warp = tid >> 5, lane = tid & 31;
    int wm = (warp >> 2) * 64;      // 2 warps in m
    int wn = (warp & 3) * 32;       // 4 warps in n
    int g  = lane >> 2, ctg = lane & 3;

    float acc[4][4][4] = {};

    // per-stage: 4 cp.async 16B for A and 4 for B per thread (16KB each tile)
    auto ldgsts = [&](int s, int buf) {
        int slab = s >> 1, koff = (s & 1) * 64;
        const __nv_bfloat16* Ap = Aslab[slab];
        const __nv_bfloat16* Wp = Wslab[slab];
#pragma unroll
        for (int l = 0; l < 4; l++) {
            int u = tid + l * 256;          // 0..1023 uint4 slots
            int row = u >> 3, kq = u & 7;   // 128 rows x 8 chunks
            int gm = m0 + row;
            int gmc = gm < Nn ? gm : 0;     // clamp; zero-fill via srcBytes=0
            int sb  = gm < Nn ? 16 : 0;
            uint32_t sa = (uint32_t)__cvta_generic_to_shared(&As[buf][row * PK + kq * 8]);
            cp16(sa, Ap + (size_t)gmc * D + koff + kq * 8, sb);
            uint32_t sbad = (uint32_t)__cvta_generic_to_shared(&Bs[buf][row * PK + kq * 8]);
            cp16(sbad, Wp + row * D + koff + kq * 8, 16);
        }
        asm volatile("cp.async.commit_group;\n" ::: "memory");
    };
    auto compute = [&](int buf) {
#pragma unroll
        for (int p = 0; p < 4; p++) {       // four k16 phases per BK=64
            uint32_t bfr[4][2];
#pragma unroll
            for (int ni = 0; ni < 4; ni++) {
                int n = wn + ni * 8 + g;
                const __nv_bfloat16* bp = &Bs[buf][n * PK + p * 16 + ctg * 2];
                bfr[ni][0] = *(const uint32_t*)bp;
                bfr[ni][1] = *(const uint32_t*)(bp + 8);
            }
#pragma unroll
            for (int mi = 0; mi < 4; mi++) {
                int r = wm + mi * 16 + g;
                const __nv_bfloat16* ap = &As[buf][r * PK + p * 16 + ctg * 2];
                uint32_t a0 = *(const uint32_t*)ap;
                uint32_t a1 = *(const uint32_t*)(ap + 8 * PK);
                uint32_t a2 = *(const uint32_t*)(ap + 8);
                uint32_t a3 = *(const uint32_t*)(ap + 8 * PK + 8);
#pragma unroll
                for (int ni = 0; ni < 4; ni++)
                    mma16816(acc[mi][ni], a0, a1, a2, a3, bfr[ni][0], bfr[ni][1]);
            }
        }
    };

    ldgsts(0, 0);
    asm volatile("cp.async.wait_group 0;\n" ::: "memory");
    __syncthreads();
    for (int s = 0; s < 12; s++) {          // 6 slabs x 2 halves
        int buf = s & 1;
        if (s < 11) ldgsts(s + 1, buf ^ 1); // copies fly during compute(s)
        compute(buf);
        if (s < 11) asm volatile("cp.async.wait_group 0;\n" ::: "memory");
        __syncthreads();
    }

    // epilogue
#pragma unroll
    for (int mi = 0; mi < 4; mi++) {
        int r0 = m0 + wm + mi * 16 + g;
        int r1 = r0 + 8;
#pragma unroll
        for (int ni = 0; ni < 4; ni++) {
            int col = wn + ni * 8 + ctg * 2;
            float2 b2 = *(const float2*)(bias + col);
            float v00 = acc[mi][ni][0] + b2.x, v01 = acc[mi][ni][1] + b2.y;
            float v10 = acc[mi][ni][2] + b2.x, v11 = acc[mi][ni][3] + b2.y;
            if (LAYER == 1) {
                v00 = fmaxf(v00, 0.f); v01 = fmaxf(v01, 0.f);
                v10 = fmaxf(v10, 0.f); v11 = fmaxf(v11, 0.f);
                if (r0 < Nn) {
                    size_t o = (size_t)r0 * D + col;
                    __nv_bfloat162 h2, l2; split2(v00, v01, h2, l2);
                    *(__nv_bfloat162*)(g_hh + o) = h2;
                    *(__nv_bfloat162*)(g_hl + o) = l2;
                }
                if (r1 < Nn) {
                    size_t o = (size_t)r1 * D + col;
                    __nv_bfloat162 h2, l2; split2(v10, v11, h2, l2);
                    *(__nv_bfloat162*)(g_hh + o) = h2;
                    *(__nv_bfloat162*)(g_hl + o) = l2;
                }
            } else {
                if (r0 < Nn) *(float2*)(outp + (size_t)r0 * D + col) = make_float2(v00, v01);
                if (r1 < Nn) *(float2*)(outp + (size_t)r1 * D + col) = make_float2(v10, v11);
            }
        }
    }
}

// ============================ launch ============================
extern "C" void kernel_launch(void* const* d_in, const int* in_sizes, int n_in,
                              void* d_out, int out_size)
{
    const float* x   = (const float*)d_in[0];
    const int*   ei  = (const int*)d_in[1];       // int32 (JAX x64 disabled)
    const float* w1l = (const float*)d_in[2];
    const float* b1  = (const float*)d_in[3];
    const float* w1r = (const float*)d_in[4];
    const float* w2l = (const float*)d_in[5];
    const float* b2  = (const float*)d_in[6];
    const float* w2r = (const float*)d_in[7];
    float*       out = (float*)d_out;

    int Nn = in_sizes[0] / D;
    int E  = in_sizes[1] / 2;
    const int* src = ei;
    const int* dst = ei + E;

    int FB = (E + 255) / 256;
    int XB = (Nn * (D / 4) + 255) / 256;
    int WB = (D * D + 255) / 256;

    k_deg<<<FB, 256>>>(dst, E, Nn);
    k_assign<<<(Nn + 255) / 256, 256>>>(Nn);
    k_fill_split<<<FB + XB + WB, 256>>>(src, dst, E, Nn, x, w1l, w1r, w2l, w2r, FB, XB);

    int aggBlocks  = (Nn * 32 + 255) / 256;
    int gemmBlocks = (Nn + 127) / 128;

    k_agg<false><<<aggBlocks, 256>>>(x, Nn);
    k_mma<1><<<gemmBlocks, 256>>>(b1, nullptr, Nn);

    k_agg<true><<<aggBlocks, 256>>>(nullptr, Nn);
    k_mma<2><<<gemmBlocks, 256>>>(b2, out, Nn);
}